// round 9
// baseline (speedup 1.0000x reference)
#include <cuda_runtime.h>
#include <math.h>

// SDF2: mesh -> voxel (inside ? distance : 0) grid. Round-9:
//   - revert to scalar round-7 body (f32x2 is half-rate on sm_100a -> neutral)
//   - NEW: plane-distance culling. |hs| (maintained anyway) lower-bounds the
//     triangle distance and is affine in z -> min over the thread's 16 z's is
//     min(|hs_0|,|hs_15|) (0 on sign change). If that^2 >= max_k md[k] for all
//     32 lanes (warp vote), skip the whole 16-k inner loop. Parity (cheap,
//     hoisted) is computed before the skip, so inside/outside is exact.
//   - warps remapped to compact 4x8x(half-z) boxes for vote coherence
//   - blocks cooperate through the global atomicMax key array: push partial
//     mins early, pull (ld.global.cg) periodically to tighten md -> skip more.
//     Stale pulls are conservative; skipped triangles provably can't improve
//     the min. Output identical every call (init kernel re-zeros keys).

#define G_DIM    32
#define N_PTS    (G_DIM * G_DIM * G_DIM)          // 32768
#define N_FACES  2048
#define N_CHUNKS 37
#define TRI_MAX  56
#define KPT      16
#define N_GROUPS (N_PTS / KPT)                    // 2048
#define THREADS  128
#define EPSF     1e-12f

// key = ~float_bits(md2): md2>=0 monotone, atomicMax, 0 == "+inf md2"
__device__ unsigned g_key[N_PTS];
__device__ unsigned g_parc[N_CHUNKS * N_GROUPS];  // per-chunk parity (plain store)

__global__ void __launch_bounds__(256)
sdf_init()
{
    int i = blockIdx.x * 256 + threadIdx.x;
    if (i < N_PTS) g_key[i] = 0u;
}

__global__ void __launch_bounds__(THREADS, 4)
sdf_main(const int* __restrict__ faces, const float* __restrict__ verts)
{
    // 9 float4 per triangle:
    // 0: ab.xyz, inv_ab   1: ac.xyz, inv_ac   2: bc.xyz, inv_bc
    // 3: A.xyz, kbc       4: B.xyz, inv_n     5: C.xyz, gram
    // 6: n.xyz, qab       7: qaa, qac, ivb, ivc   8: ihs, 15*ihs, iab, iac
    __shared__ float4 tc[9 * TRI_MAX];            // 8.1 KB

    const int start = (blockIdx.y * N_FACES) / N_CHUNKS;
    const int end   = ((blockIdx.y + 1) * N_FACES) / N_CHUNKS;
    const int ntri  = end - start;
    const float dz  = 1.0f / (float)G_DIM;

    if (threadIdx.x < ntri) {
        const int f = threadIdx.x;
        const int base = (start + f) * 3;
        const float* va  = verts + 3 * faces[base + 0];
        const float* vbv = verts + 3 * faces[base + 1];
        const float* vcv = verts + 3 * faces[base + 2];
        float Ax = va[0],  Ay = va[1],  Az = va[2];
        float Bx = vbv[0], By = vbv[1], Bz = vbv[2];
        float Cx = vcv[0], Cy = vcv[1], Cz = vcv[2];

        float abx = Bx - Ax, aby = By - Ay, abz = Bz - Az;
        float acx = Cx - Ax, acy = Cy - Ay, acz = Cz - Az;
        float bcx = Cx - Bx, bcy = Cy - By, bcz = Cz - Bz;

        float qaa = abx * abx + aby * aby + abz * abz;
        float qab = abx * acx + aby * acy + abz * acz;
        float qac = acx * acx + acy * acy + acz * acz;
        float qbc = bcx * bcx + bcy * bcy + bcz * bcz;

        float nx = aby * acz - abz * acy;
        float ny = abz * acx - abx * acz;
        float nz = abx * acy - aby * acx;
        float gram = nx * nx + ny * ny + nz * nz;
        float inv_n = rsqrtf(fmaxf(gram, EPSF));

        float ivb = (qac * abz - qab * acz) * dz;
        float ivc = (qaa * acz - qab * abz) * dz;
        float ihs = nz * dz * inv_n;

        tc[9 * f + 0] = make_float4(abx, aby, abz, __fdividef(1.0f, fmaxf(qaa, EPSF)));
        tc[9 * f + 1] = make_float4(acx, acy, acz, __fdividef(1.0f, fmaxf(qac, EPSF)));
        tc[9 * f + 2] = make_float4(bcx, bcy, bcz, __fdividef(1.0f, fmaxf(qbc, EPSF)));
        tc[9 * f + 3] = make_float4(Ax, Ay, Az, qaa - qab);   // kbc
        tc[9 * f + 4] = make_float4(Bx, By, Bz, inv_n);
        tc[9 * f + 5] = make_float4(Cx, Cy, Cz, gram);
        tc[9 * f + 6] = make_float4(nx, ny, nz, qab);
        tc[9 * f + 7] = make_float4(qaa, qac, ivb, ivc);
        tc[9 * f + 8] = make_float4(ihs, 15.0f * ihs, abz * dz, acz * dz);
    }
    __syncthreads();

    // warp-compact mapping: warp covers 4(ix) x 8(iy) x one z-half
    const int w  = threadIdx.x >> 5, l = threadIdx.x & 31;
    const int bx = blockIdx.x;                            // [0,16)
    const int ix = ((bx >> 2) << 3) + ((w >> 1) << 2) + ((l >> 3) & 3);
    const int iy = ((bx & 3) << 3) + (l & 7);
    const int zh = w & 1;
    const int iz0 = zh << 4;

    const float px  = ((float)ix  + 0.5f) * dz;
    const float py  = ((float)iy  + 0.5f) * dz;
    const float pz0 = ((float)iz0 + 0.5f) * dz;
    const int pbase = ((ix * 32 + iy) * 32) + iz0;
    const int gidx  = (ix * 32 + iy) * 2 + zh;

    float md[KPT];
    #pragma unroll
    for (int k = 0; k < KPT; ++k) md[k] = INFINITY;
    unsigned par = 0u;
    float M_up = INFINITY;

    for (int f = 0; f < ntri; ++f) {
        // cooperative push/pull schedule (uniform across warp)
        if (f == 8 || f == 28) {
            #pragma unroll
            for (int k = 0; k < KPT; ++k)
                atomicMax(&g_key[pbase + k], ~__float_as_uint(md[k]));
        }
        if (f == 8 || f == 16 || f == 28 || f == 44) {
            #pragma unroll
            for (int k = 0; k < KPT; ++k) {
                float gm = __uint_as_float(~__ldcg(&g_key[pbase + k]));
                md[k] = fminf(md[k], gm);             // NaN (unwritten) ignored
            }
            M_up = md[0];
            #pragma unroll
            for (int k = 1; k < KPT; ++k) M_up = fmaxf(M_up, md[k]);
        }

        const float4 c3 = tc[9 * f + 3];
        const float4 c4 = tc[9 * f + 4];
        const float4 c5 = tc[9 * f + 5];
        const float4 c6 = tc[9 * f + 6];
        const float4 c8 = tc[9 * f + 8];

        // ---- ray crossing (den == nz), always computed ----
        {
            float cpx2 = px - c5.x, cpy2 = py - c5.y;
            float nz = c6.z;
            float e0 = c4.y - c5.y;
            float e1 = c5.x - c4.x;
            float un = e0 * cpx2 + e1 * cpy2;
            float vn = (c5.y - c3.y) * cpx2 + (c3.x - c5.x) * cpy2;
            float wn = nz - un - vn;
            bool c2d = (fabsf(nz) >= EPSF)
                     & (un * nz >= 0.0f) & (vn * nz >= 0.0f) & (wn * nz >= 0.0f);
            if (c2d) {
                float zhit = __fdividef(un * c3.z + vn * c4.z + wn * c5.z, nz);
                float fcnt = (zhit - pz0) * (float)G_DIM;
                int n = (int)ceilf(fminf(fmaxf(fcnt, 0.0f), (float)KPT));
                par ^= (1u << n) - 1u;
            }
        }

        // ---- plane-distance cull ----
        const float apx = px - c3.x, apy = py - c3.y;
        const float apz0 = pz0 - c3.z;
        float hs = (c6.x * apx + c6.y * apy + c6.z * apz0) * c4.w;  // (n.ap)/|n|
        float hsE = hs + c8.y;                                      // hs at k=15
        float cross = hs * hsE;                                     // <0: crosses
        float m2 = fminf(hs * hs, hsE * hsE);
        bool skip = (cross >= 0.0f) & (m2 >= M_up);
        if (__all_sync(0xFFFFFFFFu, skip)) continue;

        const float4 c0 = tc[9 * f + 0];
        const float4 c1 = tc[9 * f + 1];
        const float4 c2 = tc[9 * f + 2];
        const float4 c7 = tc[9 * f + 7];
        const float gram = c5.w;

        const float bpx = px - c4.x, bpy = py - c4.y;
        float apz = apz0;
        float bpz = pz0 - c4.z;
        float d1 = c0.x * apx + c0.y * apy + c0.z * apz;
        float d2 = c1.x * apx + c1.y * apy + c1.z * apz;
        float d43 = (d2 - d1) + c3.w;
        float vb = c7.y * d1 - c6.w * d2;
        float vc = c7.x * d2 - c6.w * d1;
        const float iab = c8.z, iac = c8.w, i43 = iac - iab, ihs = c8.x;

        #pragma unroll
        for (int k = 0; k < KPT; ++k) {
            float t1 = __saturatef(d1 * c0.w);
            float rx = apx - t1 * c0.x;
            float ry = apy - t1 * c0.y;
            float rz = apz - t1 * c0.z;
            float dAB = rx * rx + ry * ry + rz * rz;
            float t2 = __saturatef(d2 * c1.w);
            rx = apx - t2 * c1.x;
            ry = apy - t2 * c1.y;
            rz = apz - t2 * c1.z;
            float dAC = rx * rx + ry * ry + rz * rz;
            float t3 = __saturatef(d43 * c2.w);
            rx = bpx - t3 * c2.x;
            ry = bpy - t3 * c2.y;
            rz = bpz - t3 * c2.z;
            float dBC = rx * rx + ry * ry + rz * rz;

            float m = fminf(fminf(dAB, dAC), dBC);

            float s = vb + vc;
            bool inter = (vb > 0.0f) & (vc > 0.0f) & (s < gram);
            float hh = hs * hs;
            m = inter ? hh : m;

            md[k] = fminf(md[k], m);

            d1 += iab; d2 += iac; d43 += i43;
            apz += dz; bpz += dz;
            hs += ihs; vb += c7.z; vc += c7.w;
        }
    }

    #pragma unroll
    for (int k = 0; k < KPT; ++k)
        atomicMax(&g_key[pbase + k], ~__float_as_uint(md[k]));
    g_parc[blockIdx.y * N_GROUPS + gidx] = par;
}

__global__ void __launch_bounds__(256)
sdf_finalize(float* __restrict__ out)
{
    int p = blockIdx.x * 256 + threadIdx.x;               // [0, 32768)
    float m = __uint_as_float(~g_key[p]);
    int gidx = (p >> 5) * 2 + ((p >> 4) & 1);
    int k = p & 15;
    unsigned par = 0u;
    #pragma unroll
    for (int c = 0; c < N_CHUNKS; ++c)
        par ^= g_parc[c * N_GROUPS + gidx];
    out[p] = ((par >> k) & 1u) ? sqrtf(m) : 0.0f;
}

extern "C" void kernel_launch(void* const* d_in, const int* in_sizes, int n_in,
                              void* d_out, int out_size)
{
    const int* faces = nullptr;
    const float* verts = nullptr;
    for (int i = 0; i < n_in; ++i) {
        if (in_sizes[i] == 3 * N_FACES)   faces = (const int*)d_in[i];
        else if (in_sizes[i] == 3 * 1026) verts = (const float*)d_in[i];
    }
    if (!faces) faces = (const int*)d_in[0];
    if (!verts) verts = (const float*)d_in[1];

    sdf_init<<<N_PTS / 256, 256>>>();
    dim3 grid(16, N_CHUNKS);                              // 592 blocks
    sdf_main<<<grid, THREADS>>>(faces, verts);
    sdf_finalize<<<N_PTS / 256, 256>>>((float*)d_out);
}